// round 2
// baseline (speedup 1.0000x reference)
#include <cuda_runtime.h>
#include <cuda_bf16.h>

#define BB   2
#define TT   2048
#define CC   1024
#define HH   16
#define DD   64
#define C3   3072

// ---------------- scratch (static device globals; no allocations) -------------
__device__ float g_qkv[BB * TT * C3];          // [B,T,3C]   50.3 MB
__device__ float g_q[BB * HH * TT * DD];       // [B,H,T,D]  16.8 MB
__device__ float g_k[BB * HH * TT * DD];
__device__ float g_v[BB * HH * TT * DD];
__device__ float g_y[BB * HH * TT * DD];

// ---------------- tiled fp32 GEMM: C[M,N] = A[M,K] @ B[K,N] + bias -----------
// BM=BN=64, BK=16, 256 threads, 4x4 microtile per thread.
// AHEADS: A is logically [M=B*T, K=H*D] but stored as g_y [B,H,T,D].
template <bool AHEADS>
__global__ void gemm_bias_kernel(const float* __restrict__ A,
                                 const float* __restrict__ Bm,
                                 const float* __restrict__ bias,
                                 float* __restrict__ Cm,
                                 int M, int N, int K)
{
    __shared__ float As[16][64];   // As[k][m]
    __shared__ float Bs[16][64];   // Bs[k][n]

    const int tid = threadIdx.x;
    const int m0 = blockIdx.y * 64;
    const int n0 = blockIdx.x * 64;

    const int ar  = tid >> 2;          // 0..63  (A tile row)
    const int ac  = (tid & 3) << 2;    // 0,4,8,12 (A tile k)
    const int brr = tid >> 4;          // 0..15  (B tile k)
    const int bc  = (tid & 15) << 2;   // 0..60  (B tile n)
    const int ty  = tid >> 4;
    const int tx  = tid & 15;

    float acc[4][4];
#pragma unroll
    for (int i = 0; i < 4; i++)
#pragma unroll
        for (int j = 0; j < 4; j++) acc[i][j] = 0.f;

    const int arow = m0 + ar;
    long aBase;
    if (AHEADS) {
        int bb = arow >> 11;           // / 2048
        int t  = arow & 2047;
        aBase = ((long)bb * HH) * (long)(TT * DD) + (long)t * DD;
    } else {
        aBase = (long)arow * K;
    }

    for (int k0 = 0; k0 < K; k0 += 16) {
        float4 av;
        if (AHEADS) {
            int c = k0 + ac;
            int h = c >> 6, d = c & 63;
            av = *(const float4*)&A[aBase + (long)h * (TT * DD) + d];
        } else {
            av = *(const float4*)&A[aBase + k0 + ac];
        }
        As[ac + 0][ar] = av.x;
        As[ac + 1][ar] = av.y;
        As[ac + 2][ar] = av.z;
        As[ac + 3][ar] = av.w;

        float4 bv = *(const float4*)&Bm[(long)(k0 + brr) * N + n0 + bc];
        *(float4*)&Bs[brr][bc] = bv;

        __syncthreads();
#pragma unroll
        for (int kk = 0; kk < 16; kk++) {
            float4 a = *(const float4*)&As[kk][ty << 2];
            float4 b = *(const float4*)&Bs[kk][tx << 2];
            float aa[4] = {a.x, a.y, a.z, a.w};
            float bb4[4] = {b.x, b.y, b.z, b.w};
#pragma unroll
            for (int i = 0; i < 4; i++)
#pragma unroll
                for (int j = 0; j < 4; j++) acc[i][j] += aa[i] * bb4[j];
        }
        __syncthreads();
    }

#pragma unroll
    for (int i = 0; i < 4; i++) {
        long row = m0 + (ty << 2) + i;
#pragma unroll
        for (int j = 0; j < 4; j++) {
            int col = n0 + (tx << 2) + j;
            Cm[row * N + col] = acc[i][j] + bias[col];
        }
    }
}

// ---------------- RoPE + scatter to head-major layout ------------------------
// qkv [B,T,3C] -> g_q/g_k (with RoPE) and g_v, all [B,H,T,D].
__global__ void rope_scatter_kernel(const float* __restrict__ qkv,
                                    const float* __restrict__ cosT,
                                    const float* __restrict__ sinT)
{
    // one thread per (b,h,t,pair): idx = ((b*H + h)*T + t)*32 + i
    int idx = blockIdx.x * blockDim.x + threadIdx.x;
    const int total = BB * HH * TT * (DD / 2);
    if (idx >= total) return;

    int i  = idx & 31;
    int t  = (idx >> 5) & (TT - 1);
    int hh = (idx >> 5) / TT;
    int h  = hh & (HH - 1);
    int b  = hh >> 4;

    float c = cosT[t * 32 + i];
    float s = sinT[t * 32 + i];

    const float* base = qkv + (long)(b * TT + t) * C3 + h * DD;
    long oBase = ((long)(b * HH + h) * TT + t) * DD;

    float q1 = base[2 * i], q2 = base[2 * i + 1];
    g_q[oBase + 2 * i]     = q1 * c - q2 * s;
    g_q[oBase + 2 * i + 1] = q1 * s + q2 * c;

    float k1 = base[CC + 2 * i], k2 = base[CC + 2 * i + 1];
    g_k[oBase + 2 * i]     = k1 * c - k2 * s;
    g_k[oBase + 2 * i + 1] = k1 * s + k2 * c;

    float v1 = base[2 * CC + 2 * i], v2 = base[2 * CC + 2 * i + 1];
    g_v[oBase + 2 * i]     = v1;
    g_v[oBase + 2 * i + 1] = v2;
}

// ---------------- causal flash attention (fp32) ------------------------------
// Per block: one (b,h) and one 64-query tile; online softmax over 64-key tiles.
// smem: Qt[64][68], Kt[64][68], Pt[64][68], V[64][64]  (transposed tiles,
// padded rows for conflict-free + 16B-aligned float4 reads).
#define SPAD 68
#define SM_QT 0
#define SM_KT (64 * SPAD)
#define SM_PT (2 * 64 * SPAD)
#define SM_V  (3 * 64 * SPAD)
#define FLASH_SMEM ((3 * 64 * SPAD + 64 * 64) * 4)

__global__ void flash_kernel(const float* __restrict__ Q,
                             const float* __restrict__ Kg,
                             const float* __restrict__ Vg,
                             float* __restrict__ Y)
{
    extern __shared__ float sm[];
    const int tid = threadIdx.x;
    const int q0  = blockIdx.x * 64;
    const int bh  = blockIdx.y;

    const float* Qb = Q  + (long)bh * TT * DD;
    const float* Kb = Kg + (long)bh * TT * DD;
    const float* Vb = Vg + (long)bh * TT * DD;

    // load Q tile transposed: sQt[d][r] = Q[q0+r][d]
#pragma unroll
    for (int it = 0; it < 16; it++) {
        int e = tid + it * 256;
        int r = e >> 6, d = e & 63;
        sm[SM_QT + d * SPAD + r] = Qb[(long)(q0 + r) * DD + d];
    }

    const int ty = tid >> 4;
    const int tx = tid & 15;
    const float scale = 0.125f;   // 64^-0.5

    float o[4][4];
    float mrow[4], lrow[4];
#pragma unroll
    for (int i = 0; i < 4; i++) {
        mrow[i] = -1e30f;
        lrow[i] = 0.f;
#pragma unroll
        for (int j = 0; j < 4; j++) o[i][j] = 0.f;
    }

    for (int kv0 = 0; kv0 < q0 + 64; kv0 += 64) {
        __syncthreads();   // previous iter's reads of Kt/V/Pt done
        // load K transposed + V natural
#pragma unroll
        for (int it = 0; it < 16; it++) {
            int e = tid + it * 256;
            int s = e >> 6, d = e & 63;
            float kvK = Kb[(long)(kv0 + s) * DD + d];
            float kvV = Vb[(long)(kv0 + s) * DD + d];
            sm[SM_KT + d * SPAD + s] = kvK;
            sm[SM_V + s * 64 + d]    = kvV;
        }
        __syncthreads();

        // S = Q @ K^T  (per-thread 4x4)
        float s4[4][4];
#pragma unroll
        for (int i = 0; i < 4; i++)
#pragma unroll
            for (int j = 0; j < 4; j++) s4[i][j] = 0.f;

#pragma unroll 8
        for (int d = 0; d < 64; d++) {
            float4 a = *(const float4*)&sm[SM_QT + d * SPAD + (ty << 2)];
            float4 b = *(const float4*)&sm[SM_KT + d * SPAD + (tx << 2)];
            float aa[4] = {a.x, a.y, a.z, a.w};
            float bb4[4] = {b.x, b.y, b.z, b.w};
#pragma unroll
            for (int i = 0; i < 4; i++)
#pragma unroll
                for (int j = 0; j < 4; j++) s4[i][j] += aa[i] * bb4[j];
        }

        // scale + causal mask (only diagonal tile needs masking)
        if (kv0 == q0) {
#pragma unroll
            for (int i = 0; i < 4; i++)
#pragma unroll
                for (int j = 0; j < 4; j++) {
                    int qi = (ty << 2) + i, ki = (tx << 2) + j;
                    s4[i][j] = (ki > qi) ? -1e30f : s4[i][j] * scale;
                }
        } else {
#pragma unroll
            for (int i = 0; i < 4; i++)
#pragma unroll
                for (int j = 0; j < 4; j++) s4[i][j] *= scale;
        }

        // online softmax: per-row reduce over 16 lanes (tx dimension)
#pragma unroll
        for (int i = 0; i < 4; i++) {
            float mx = fmaxf(fmaxf(s4[i][0], s4[i][1]), fmaxf(s4[i][2], s4[i][3]));
            mx = fmaxf(mx, __shfl_xor_sync(0xffffffffu, mx, 1, 16));
            mx = fmaxf(mx, __shfl_xor_sync(0xffffffffu, mx, 2, 16));
            mx = fmaxf(mx, __shfl_xor_sync(0xffffffffu, mx, 4, 16));
            mx = fmaxf(mx, __shfl_xor_sync(0xffffffffu, mx, 8, 16));
            float mnew  = fmaxf(mrow[i], mx);
            float alpha = __expf(mrow[i] - mnew);
            float rs = 0.f;
#pragma unroll
            for (int j = 0; j < 4; j++) {
                float p = __expf(s4[i][j] - mnew);
                sm[SM_PT + ((tx << 2) + j) * SPAD + (ty << 2) + i] = p;  // P^T
                rs += p;
            }
            rs += __shfl_xor_sync(0xffffffffu, rs, 1, 16);
            rs += __shfl_xor_sync(0xffffffffu, rs, 2, 16);
            rs += __shfl_xor_sync(0xffffffffu, rs, 4, 16);
            rs += __shfl_xor_sync(0xffffffffu, rs, 8, 16);
            lrow[i] = lrow[i] * alpha + rs;
            mrow[i] = mnew;
#pragma unroll
            for (int j = 0; j < 4; j++) o[i][j] *= alpha;
        }
        __syncthreads();

        // O += P @ V
#pragma unroll 8
        for (int s = 0; s < 64; s++) {
            float4 a = *(const float4*)&sm[SM_PT + s * SPAD + (ty << 2)];
            float4 b = *(const float4*)&sm[SM_V + s * 64 + (tx << 2)];
            float aa[4] = {a.x, a.y, a.z, a.w};
            float bb4[4] = {b.x, b.y, b.z, b.w};
#pragma unroll
            for (int i = 0; i < 4; i++)
#pragma unroll
                for (int j = 0; j < 4; j++) o[i][j] += aa[i] * bb4[j];
        }
    }

    float* Yb = Y + (long)bh * TT * DD;
#pragma unroll
    for (int i = 0; i < 4; i++) {
        float inv = 1.f / lrow[i];
        int r = q0 + (ty << 2) + i;
#pragma unroll
        for (int j = 0; j < 4; j++)
            Yb[(long)r * DD + (tx << 2) + j] = o[i][j] * inv;
    }
}

// ---------------- launcher ----------------------------------------------------
extern "C" void kernel_launch(void* const* d_in, const int* in_sizes, int n_in,
                              void* d_out, int out_size)
{
    const float* x     = (const float*)d_in[0];   // [2,2048,1024]
    const float* Wqkv  = (const float*)d_in[1];   // [1024,3072]
    const float* bqkv  = (const float*)d_in[2];   // [3072]
    const float* Wproj = (const float*)d_in[3];   // [1024,1024]
    const float* bproj = (const float*)d_in[4];   // [1024]
    const float* cosT  = (const float*)d_in[5];   // [2048,32]
    const float* sinT  = (const float*)d_in[6];   // [2048,32]
    float* out = (float*)d_out;                   // [2,2048,1024]

    float *qkv, *q, *k, *v, *y;
    cudaGetSymbolAddress((void**)&qkv, g_qkv);
    cudaGetSymbolAddress((void**)&q,   g_q);
    cudaGetSymbolAddress((void**)&k,   g_k);
    cudaGetSymbolAddress((void**)&v,   g_v);
    cudaGetSymbolAddress((void**)&y,   g_y);

    static bool attr_set = false;
    if (!attr_set) {
        cudaFuncSetAttribute(flash_kernel,
                             cudaFuncAttributeMaxDynamicSharedMemorySize,
                             FLASH_SMEM);
        attr_set = true;
    }

    const int M = BB * TT;   // 4096

    // 1) QKV projection
    gemm_bias_kernel<false><<<dim3(C3 / 64, M / 64), 256>>>(
        x, Wqkv, bqkv, qkv, M, C3, CC);

    // 2) RoPE + scatter to [B,H,T,D]
    {
        int total = BB * HH * TT * (DD / 2);
        rope_scatter_kernel<<<(total + 255) / 256, 256>>>(qkv, cosT, sinT);
    }

    // 3) causal flash attention
    flash_kernel<<<dim3(TT / 64, BB * HH), 256, FLASH_SMEM>>>(q, k, v, y);

    // 4) output projection (reads y in head-major layout)
    gemm_bias_kernel<true><<<dim3(CC / 64, M / 64), 256>>>(
        y, Wproj, bproj, out, M, CC, CC);
}

// round 6
// speedup vs baseline: 1.6292x; 1.6292x over previous
#include <cuda_runtime.h>
#include <cuda_bf16.h>
#include <cstdint>

#define BB   2
#define TT   2048
#define CC   1024
#define HH   16
#define DD   64
#define C3   3072
#define MM   (BB * TT)        // 4096

// ---------------- scratch (static device globals; no allocations) -------------
__device__ float g_qkv[BB * TT * C3];              // [B,T,3C] fp32
__device__ float g_q[BB * HH * TT * DD];           // [B,H,T,D]
__device__ float g_k[BB * HH * TT * DD];
__device__ float g_v[BB * HH * TT * DD];

__device__ __nv_bfloat16 g_xhi[MM * CC];           // x split  [M,K]
__device__ __nv_bfloat16 g_xlo[MM * CC];
__device__ __nv_bfloat16 g_wqhi[C3 * CC];          // Wqkv^T split [N,K]
__device__ __nv_bfloat16 g_wqlo[C3 * CC];
__device__ __nv_bfloat16 g_wphi[CC * CC];          // Wproj^T split [N,K]
__device__ __nv_bfloat16 g_wplo[CC * CC];
__device__ __nv_bfloat16 g_yhi[MM * CC];           // attention out split [B,T,C]
__device__ __nv_bfloat16 g_ylo[MM * CC];

// ---------------- helpers ------------------------------------------------------
__device__ __forceinline__ uint32_t smem_u32(const void* p) {
    uint32_t a;
    asm("{ .reg .u64 t; cvta.to.shared.u64 t, %1; cvt.u32.u64 %0, t; }"
        : "=r"(a) : "l"(p));
    return a;
}

__device__ __forceinline__ void ldsm_x4(uint32_t r[4], uint32_t addr) {
    asm volatile("ldmatrix.sync.aligned.m8n8.x4.shared.b16 {%0,%1,%2,%3}, [%4];"
                 : "=r"(r[0]), "=r"(r[1]), "=r"(r[2]), "=r"(r[3]) : "r"(addr));
}

__device__ __forceinline__ void mma_bf16(float d[4], const uint32_t a[4],
                                         const uint32_t b[2]) {
    asm volatile(
        "mma.sync.aligned.m16n8k16.row.col.f32.bf16.bf16.f32 "
        "{%0,%1,%2,%3}, {%4,%5,%6,%7}, {%8,%9}, {%0,%1,%2,%3};"
        : "+f"(d[0]), "+f"(d[1]), "+f"(d[2]), "+f"(d[3])
        : "r"(a[0]), "r"(a[1]), "r"(a[2]), "r"(a[3]), "r"(b[0]), "r"(b[1]));
}

// ---------------- pre-pass: fp32 -> bf16 hi/lo split --------------------------
__global__ void split_kernel(const float* __restrict__ A,
                             __nv_bfloat16* __restrict__ hi,
                             __nv_bfloat16* __restrict__ lo, int n)
{
    int i = blockIdx.x * 256 + threadIdx.x;
    if (i < n) {
        float v = A[i];
        __nv_bfloat16 h = __float2bfloat16(v);
        hi[i] = h;
        lo[i] = __float2bfloat16(v - __bfloat162float(h));
    }
}

// transpose + split: W [K,N] fp32 -> hi/lo [N,K] bf16
__global__ void tsplit_kernel(const float* __restrict__ W,
                              __nv_bfloat16* __restrict__ hi,
                              __nv_bfloat16* __restrict__ lo, int K, int N)
{
    __shared__ float t[32][33];
    int k0 = blockIdx.y * 32, n0 = blockIdx.x * 32;
    int tx = threadIdx.x, ty = threadIdx.y;   // block (32,8)
#pragma unroll
    for (int i = 0; i < 32; i += 8)
        t[ty + i][tx] = W[(size_t)(k0 + ty + i) * N + n0 + tx];
    __syncthreads();
#pragma unroll
    for (int i = 0; i < 32; i += 8) {
        float v = t[tx][ty + i];             // = W[k0+tx][n0+ty+i]
        size_t o = (size_t)(n0 + ty + i) * K + k0 + tx;
        __nv_bfloat16 h = __float2bfloat16(v);
        hi[o] = h;
        lo[o] = __float2bfloat16(v - __bfloat162float(h));
    }
}

// ---------------- mma.sync bf16 split GEMM ------------------------------------
// C[M,N] = A[M,K] @ Bt[N,K]^T + bias, fp32 accum.
// CTA tile 128x64, BK=64, 8 warps (4m x 2n), warp tile 32x32.
#define GBM 128
#define GBN 64
#define GBK 64
#define KPAD 72                              // bf16 elems per smem row (144 B)
#define OFF_AH 0
#define OFF_AL (128 * KPAD * 2)
#define OFF_BH (2 * 128 * KPAD * 2)
#define OFF_BL (2 * 128 * KPAD * 2 + 64 * KPAD * 2)
#define GSMEM  (2 * 128 * KPAD * 2 + 2 * 64 * KPAD * 2)   // 55296 B

__global__ void __launch_bounds__(256)
gemm_mma_kernel(const __nv_bfloat16* __restrict__ Ahi,
                const __nv_bfloat16* __restrict__ Alo,
                const __nv_bfloat16* __restrict__ Bhi,
                const __nv_bfloat16* __restrict__ Blo,
                const float* __restrict__ bias,
                float* __restrict__ Cm,
                int N, int K)
{
    extern __shared__ __align__(16) unsigned char smem[];
    __nv_bfloat16* sAh = (__nv_bfloat16*)(smem + OFF_AH);
    __nv_bfloat16* sAl = (__nv_bfloat16*)(smem + OFF_AL);
    __nv_bfloat16* sBh = (__nv_bfloat16*)(smem + OFF_BH);
    __nv_bfloat16* sBl = (__nv_bfloat16*)(smem + OFF_BL);
    const uint32_t sb = smem_u32(smem);

    const int tid  = threadIdx.x;
    const int lane = tid & 31;
    const int w    = tid >> 5;
    const int m_base = (w & 3) * 32;    // warp row offset in CTA tile
    const int n_base = (w >> 2) * 32;   // warp col offset

    const int m0 = blockIdx.y * GBM;
    const int n0 = blockIdx.x * GBN;

    float d[2][4][4];
#pragma unroll
    for (int i = 0; i < 2; i++)
#pragma unroll
        for (int j = 0; j < 4; j++)
#pragma unroll
            for (int r = 0; r < 4; r++) d[i][j][r] = 0.f;

    // per-lane ldmatrix address components (constant across chunks)
    const int a_m   = m_base + (lane & 7) + ((lane >> 3) & 1) * 8;
    const int a_khi = (lane >> 4) * 8;
    const int b_g   = lane >> 3;
    const int b_n8  = (b_g >> 1) * 8 + (lane & 7);
    const int b_k8  = (b_g & 1) * 8;

    for (int k0 = 0; k0 < K; k0 += GBK) {
        // ---- load chunk into smem (144B padded rows) ----
#pragma unroll
        for (int it = 0; it < 4; it++) {
            int u = tid + it * 256;          // 0..1023
            int row = u >> 3, c8 = u & 7;
            size_t g = (size_t)(m0 + row) * K + k0 + c8 * 8;
            int s = row * KPAD + c8 * 8;
            *(uint4*)(sAh + s) = *(const uint4*)(Ahi + g);
            *(uint4*)(sAl + s) = *(const uint4*)(Alo + g);
        }
#pragma unroll
        for (int it = 0; it < 2; it++) {
            int u = tid + it * 256;          // 0..511
            int row = u >> 3, c8 = u & 7;
            size_t g = (size_t)(n0 + row) * K + k0 + c8 * 8;
            int s = row * KPAD + c8 * 8;
            *(uint4*)(sBh + s) = *(const uint4*)(Bhi + g);
            *(uint4*)(sBl + s) = *(const uint4*)(Blo + g);
        }
        __syncthreads();

        // ---- 4 k-steps of 16 ----
#pragma unroll
        for (int ks = 0; ks < 4; ks++) {
            const int koff = ks * 16;
            uint32_t ah[2][4], al[2][4], bh[4][2], bl[4][2];
#pragma unroll
            for (int mf = 0; mf < 2; mf++) {
                uint32_t off = (uint32_t)((a_m + mf * 16) * KPAD + koff + a_khi) * 2;
                ldsm_x4(ah[mf], sb + OFF_AH + off);
                ldsm_x4(al[mf], sb + OFF_AL + off);
            }
#pragma unroll
            for (int pr = 0; pr < 2; pr++) {
                uint32_t off = (uint32_t)((n_base + pr * 16 + b_n8) * KPAD + koff + b_k8) * 2;
                uint32_t rh[4], rl[4];
                ldsm_x4(rh, sb + OFF_BH + off);
                ldsm_x4(rl, sb + OFF_BL + off);
                bh[pr * 2 + 0][0] = rh[0]; bh[pr * 2 + 0][1] = rh[1];
                bh[pr * 2 + 1][0] = rh[2]; bh[pr * 2 + 1][1] = rh[3];
                bl[pr * 2 + 0][0] = rl[0]; bl[pr * 2 + 0][1] = rl[1];
                bl[pr * 2 + 1][0] = rl[2]; bl[pr * 2 + 1][1] = rl[3];
            }
#pragma unroll
            for (int mf = 0; mf < 2; mf++)
#pragma unroll
                for (int nf = 0; nf < 4; nf++) {
                    mma_bf16(d[mf][nf], ah[mf], bh[nf]);
                    mma_bf16(d[mf][nf], ah[mf], bl[nf]);
                    mma_bf16(d[mf][nf], al[mf], bh[nf]);
                }
        }
        __syncthreads();
    }

    // ---- epilogue ----
#pragma unroll
    for (int mf = 0; mf < 2; mf++) {
#pragma unroll
        for (int nf = 0; nf < 4; nf++) {
            int row = m0 + m_base + mf * 16 + (lane >> 2);
            int col = n0 + n_base + nf * 8 + 2 * (lane & 3);
            float bx = bias[col], by = bias[col + 1];
            float2 v0 = {d[mf][nf][0] + bx, d[mf][nf][1] + by};
            float2 v1 = {d[mf][nf][2] + bx, d[mf][nf][3] + by};
            *(float2*)&Cm[(size_t)row * N + col]       = v0;
            *(float2*)&Cm[(size_t)(row + 8) * N + col] = v1;
        }
    }
}

// ---------------- RoPE + scatter to head-major layout ------------------------
__global__ void rope_scatter_kernel(const float* __restrict__ qkv,
                                    const float* __restrict__ cosT,
                                    const float* __restrict__ sinT)
{
    int idx = blockIdx.x * blockDim.x + threadIdx.x;
    const int total = BB * HH * TT * (DD / 2);
    if (idx >= total) return;

    int i  = idx & 31;
    int t  = (idx >> 5) & (TT - 1);
    int hh = (idx >> 5) / TT;
    int h  = hh & (HH - 1);
    int b  = hh >> 4;

    float c = cosT[t * 32 + i];
    float s = sinT[t * 32 + i];

    const float* base = qkv + (size_t)(b * TT + t) * C3 + h * DD;
    size_t oBase = ((size_t)(b * HH + h) * TT + t) * DD;

    float q1 = base[2 * i], q2 = base[2 * i + 1];
    g_q[oBase + 2 * i]     = q1 * c - q2 * s;
    g_q[oBase + 2 * i + 1] = q1 * s + q2 * c;

    float k1 = base[CC + 2 * i], k2 = base[CC + 2 * i + 1];
    g_k[oBase + 2 * i]     = k1 * c - k2 * s;
    g_k[oBase + 2 * i + 1] = k1 * s + k2 * c;

    g_v[oBase + 2 * i]     = base[2 * CC + 2 * i];
    g_v[oBase + 2 * i + 1] = base[2 * CC + 2 * i + 1];
}

// ---------------- causal flash attention (fp32) ------------------------------
#define SPAD 68
#define SM_QT 0
#define SM_KT (64 * SPAD)
#define SM_PT (2 * 64 * SPAD)
#define SM_V  (3 * 64 * SPAD)
#define FLASH_SMEM ((3 * 64 * SPAD + 64 * 64) * 4)

__global__ void flash_kernel(const float* __restrict__ Q,
                             const float* __restrict__ Kg,
                             const float* __restrict__ Vg)
{
    extern __shared__ float sm[];
    const int tid = threadIdx.x;
    const int q0  = blockIdx.x * 64;
    const int bh  = blockIdx.y;

    const float* Qb = Q  + (size_t)bh * TT * DD;
    const float* Kb = Kg + (size_t)bh * TT * DD;
    const float* Vb = Vg + (size_t)bh * TT * DD;

#pragma unroll
    for (int it = 0; it < 16; it++) {
        int e = tid + it * 256;
        int r = e >> 6, d = e & 63;
        sm[SM_QT + d * SPAD + r] = Qb[(size_t)(q0 + r) * DD + d];
    }

    const int ty = tid >> 4;
    const int tx = tid & 15;
    const float scale = 0.125f;

    float o[4][4];
    float mrow[4], lrow[4];
#pragma unroll
    for (int i = 0; i < 4; i++) {
        mrow[i] = -1e30f;
        lrow[i] = 0.f;
#pragma unroll
        for (int j = 0; j < 4; j++) o[i][j] = 0.f;
    }

    for (int kv0 = 0; kv0 < q0 + 64; kv0 += 64) {
        __syncthreads();
#pragma unroll
        for (int it = 0; it < 16; it++) {
            int e = tid + it * 256;
            int s = e >> 6, d = e & 63;
            sm[SM_KT + d * SPAD + s] = Kb[(size_t)(kv0 + s) * DD + d];
            sm[SM_V + s * 64 + d]    = Vb[(size_t)(kv0 + s) * DD + d];
        }
        __syncthreads();

        float s4[4][4];
#pragma unroll
        for (int i = 0; i < 4; i++)
#pragma unroll
            for (int j = 0; j < 4; j++) s4[i][j] = 0.f;

#pragma unroll 8
        for (int d = 0; d < 64; d++) {
            float4 a = *(const float4*)&sm[SM_QT + d * SPAD + (ty << 2)];
            float4 b = *(const float4*)&sm[SM_KT + d * SPAD + (tx << 2)];
            float aa[4] = {a.x, a.y, a.z, a.w};
            float bb4[4] = {b.x, b.y, b.z, b.w};
#pragma unroll
            for (int i = 0; i < 4; i++)
#pragma unroll
                for (int j = 0; j < 4; j++) s4[i][j] += aa[i] * bb4[j];
        }

        if (kv0 == q0) {
#pragma unroll
            for (int i = 0; i < 4; i++)
#pragma unroll
                for (int j = 0; j < 4; j++) {
                    int qi = (ty << 2) + i, ki = (tx << 2) + j;
                    s4[i][j] = (ki > qi) ? -1e30f : s4[i][j] * scale;
                }
        } else {
#pragma unroll
            for (int i = 0; i < 4; i++)
#pragma unroll
                for (int j = 0; j < 4; j++) s4[i][j] *= scale;
        }

#pragma unroll
        for (int i = 0; i < 4; i++) {
            float mx = fmaxf(fmaxf(s4[i][0], s4[i][1]), fmaxf(s4[i][2], s4[i][3]));
            mx = fmaxf(mx, __shfl_xor_sync(0xffffffffu, mx, 1, 16));
            mx = fmaxf(mx, __shfl_xor_sync(0xffffffffu, mx, 2, 16));
            mx = fmaxf(mx, __shfl_xor_sync(0xffffffffu, mx, 4, 16));
            mx = fmaxf(mx, __shfl_xor_sync(0xffffffffu, mx, 8, 16));
            float mnew  = fmaxf(mrow[i], mx);
            float alpha = __expf(mrow[i] - mnew);
            float rs = 0.f;
#pragma unroll
            for (int j = 0; j < 4; j++) {
                float p = __expf(s4[i][j] - mnew);
                sm[SM_PT + ((tx << 2) + j) * SPAD + (ty << 2) + i] = p;
                rs += p;
            }
            rs += __shfl_xor_sync(0xffffffffu, rs, 1, 16);
            rs += __shfl_xor_sync(0xffffffffu, rs, 2, 16);
            rs += __shfl_xor_sync(0xffffffffu, rs, 4, 16);
            rs += __shfl_xor_sync(0xffffffffu, rs, 8, 16);
            lrow[i] = lrow[i] * alpha + rs;
            mrow[i] = mnew;
#pragma unroll
            for (int j = 0; j < 4; j++) o[i][j] *= alpha;
        }
        __syncthreads();

#pragma unroll 8
        for (int s = 0; s < 64; s++) {
            float4 a = *(const float4*)&sm[SM_PT + s * SPAD + (ty << 2)];
            float4 b = *(const float4*)&sm[SM_V + s * 64 + (tx << 2)];
            float aa[4] = {a.x, a.y, a.z, a.w};
            float bb4[4] = {b.x, b.y, b.z, b.w};
#pragma unroll
            for (int i = 0; i < 4; i++)
#pragma unroll
                for (int j = 0; j < 4; j++) o[i][j] += aa[i] * bb4[j];
        }
    }

    // write attention output directly as bf16 hi/lo in [B,T,C] layout
    int b = bh >> 4, h = bh & 15;
#pragma unroll
    for (int i = 0; i < 4; i++) {
        float inv = 1.f / lrow[i];
        int r = q0 + (ty << 2) + i;
        size_t base = ((size_t)(b * TT + r)) * CC + h * DD;
#pragma unroll
        for (int j = 0; j < 4; j++) {
            float val = o[i][j] * inv;
            __nv_bfloat16 hi = __float2bfloat16(val);
            g_yhi[base + (tx << 2) + j] = hi;
            g_ylo[base + (tx << 2) + j] = __float2bfloat16(val - __bfloat162float(hi));
        }
    }
}

// ---------------- launcher ----------------------------------------------------
extern "C" void kernel_launch(void* const* d_in, const int* in_sizes, int n_in,
                              void* d_out, int out_size)
{
    const float* x     = (const float*)d_in[0];
    const float* Wqkv  = (const float*)d_in[1];
    const float* bqkv  = (const float*)d_in[2];
    const float* Wproj = (const float*)d_in[3];
    const float* bproj = (const float*)d_in[4];
    const float* cosT  = (const float*)d_in[5];
    const float* sinT  = (const float*)d_in[6];
    float* out = (float*)d_out;

    float *qkv, *q, *k, *v;
    __nv_bfloat16 *xhi, *xlo, *wqhi, *wqlo, *wphi, *wplo, *yhi, *ylo;
    cudaGetSymbolAddress((void**)&qkv,  g_qkv);
    cudaGetSymbolAddress((void**)&q,    g_q);
    cudaGetSymbolAddress((void**)&k,    g_k);
    cudaGetSymbolAddress((void**)&v,    g_v);
    cudaGetSymbolAddress((void**)&xhi,  g_xhi);
    cudaGetSymbolAddress((void**)&xlo,  g_xlo);
    cudaGetSymbolAddress((void**)&wqhi, g_wqhi);
    cudaGetSymbolAddress((void**)&wqlo, g_wqlo);
    cudaGetSymbolAddress((void**)&wphi, g_wphi);
    cudaGetSymbolAddress((void**)&wplo, g_wplo);
    cudaGetSymbolAddress((void**)&yhi,  g_yhi);
    cudaGetSymbolAddress((void**)&ylo,  g_ylo);

    static bool attr_set = false;
    if (!attr_set) {
        cudaFuncSetAttribute(flash_kernel,
                             cudaFuncAttributeMaxDynamicSharedMemorySize, FLASH_SMEM);
        cudaFuncSetAttribute(gemm_mma_kernel,
                             cudaFuncAttributeMaxDynamicSharedMemorySize, GSMEM);
        attr_set = true;
    }

    // pre-pass: split x; transpose+split weights
    split_kernel<<<(MM * CC + 255) / 256, 256>>>(x, xhi, xlo, MM * CC);
    tsplit_kernel<<<dim3(C3 / 32, CC / 32), dim3(32, 8)>>>(Wqkv, wqhi, wqlo, CC, C3);
    tsplit_kernel<<<dim3(CC / 32, CC / 32), dim3(32, 8)>>>(Wproj, wphi, wplo, CC, CC);

    // 1) QKV projection (tensor cores, mma.sync)
    gemm_mma_kernel<<<dim3(C3 / GBN, MM / GBM), 256, GSMEM>>>(
        xhi, xlo, wqhi, wqlo, bqkv, qkv, C3, CC);

    // 2) RoPE + scatter
    {
        int total = BB * HH * TT * (DD / 2);
        rope_scatter_kernel<<<(total + 255) / 256, 256>>>(qkv, cosT, sinT);
    }

    // 3) causal flash attention (writes yhi/ylo in [B,T,C])
    flash_kernel<<<dim3(TT / 64, BB * HH), 256, FLASH_SMEM>>>(q, k, v);

    // 4) output projection (tensor cores, mma.sync)
    gemm_mma_kernel<<<dim3(CC / GBN, MM / GBM), 256, GSMEM>>>(
        yhi, ylo, wphi, wplo, bproj, out, CC, CC);
}

// round 7
// speedup vs baseline: 2.8091x; 1.7243x over previous
#include <cuda_runtime.h>
#include <cuda_bf16.h>
#include <cstdint>

#define BB   2
#define TT   2048
#define CC   1024
#define HH   16
#define DD   64
#define C3   3072
#define MM   (BB * TT)        // 4096

// ---------------- scratch (static device globals; no allocations) -------------
__device__ float g_qkv[BB * TT * C3];              // [B,T,3C] fp32

__device__ __nv_bfloat16 g_xhi[MM * CC];           // x split  [M,K]
__device__ __nv_bfloat16 g_xlo[MM * CC];
__device__ __nv_bfloat16 g_wqhi[C3 * CC];          // Wqkv^T split [N,K]
__device__ __nv_bfloat16 g_wqlo[C3 * CC];
__device__ __nv_bfloat16 g_wphi[CC * CC];          // Wproj^T split [N,K]
__device__ __nv_bfloat16 g_wplo[CC * CC];
__device__ __nv_bfloat16 g_yhi[MM * CC];           // attention out split [B,T,C]
__device__ __nv_bfloat16 g_ylo[MM * CC];

// Q/K/V bf16 hi/lo in [B,H,T,D] (Q pre-scaled by 1/8)
__device__ __nv_bfloat16 g_qh[MM * CC];
__device__ __nv_bfloat16 g_ql[MM * CC];
__device__ __nv_bfloat16 g_kh[MM * CC];
__device__ __nv_bfloat16 g_kl[MM * CC];
__device__ __nv_bfloat16 g_vh[MM * CC];
__device__ __nv_bfloat16 g_vl[MM * CC];

// ---------------- helpers ------------------------------------------------------
__device__ __forceinline__ uint32_t smem_u32(const void* p) {
    uint32_t a;
    asm("{ .reg .u64 t; cvta.to.shared.u64 t, %1; cvt.u32.u64 %0, t; }"
        : "=r"(a) : "l"(p));
    return a;
}

__device__ __forceinline__ void ldsm_x4(uint32_t r[4], uint32_t addr) {
    asm volatile("ldmatrix.sync.aligned.m8n8.x4.shared.b16 {%0,%1,%2,%3}, [%4];"
                 : "=r"(r[0]), "=r"(r[1]), "=r"(r[2]), "=r"(r[3]) : "r"(addr));
}

__device__ __forceinline__ void ldsm_x4_t(uint32_t r[4], uint32_t addr) {
    asm volatile("ldmatrix.sync.aligned.m8n8.x4.trans.shared.b16 {%0,%1,%2,%3}, [%4];"
                 : "=r"(r[0]), "=r"(r[1]), "=r"(r[2]), "=r"(r[3]) : "r"(addr));
}

__device__ __forceinline__ void mma_bf16(float d[4], const uint32_t a[4],
                                         const uint32_t b[2]) {
    asm volatile(
        "mma.sync.aligned.m16n8k16.row.col.f32.bf16.bf16.f32 "
        "{%0,%1,%2,%3}, {%4,%5,%6,%7}, {%8,%9}, {%0,%1,%2,%3};"
        : "+f"(d[0]), "+f"(d[1]), "+f"(d[2]), "+f"(d[3])
        : "r"(a[0]), "r"(a[1]), "r"(a[2]), "r"(a[3]), "r"(b[0]), "r"(b[1]));
}

// split two floats into packed bf16x2 hi + lo(residual)
__device__ __forceinline__ void split2(float a, float b, uint32_t& hi, uint32_t& lo) {
    __nv_bfloat162 h = __floats2bfloat162_rn(a, b);
    hi = *(uint32_t*)&h;
    float ra = a - __bfloat162float(h.x);
    float rb = b - __bfloat162float(h.y);
    __nv_bfloat162 l2 = __floats2bfloat162_rn(ra, rb);
    lo = *(uint32_t*)&l2;
}

// ---------------- pre-pass: fp32 -> bf16 hi/lo split --------------------------
__global__ void split_kernel(const float* __restrict__ A,
                             __nv_bfloat16* __restrict__ hi,
                             __nv_bfloat16* __restrict__ lo, int n)
{
    int i = blockIdx.x * 256 + threadIdx.x;
    if (i < n) {
        float v = A[i];
        __nv_bfloat16 h = __float2bfloat16(v);
        hi[i] = h;
        lo[i] = __float2bfloat16(v - __bfloat162float(h));
    }
}

// transpose + split: W [K,N] fp32 -> hi/lo [N,K] bf16
__global__ void tsplit_kernel(const float* __restrict__ W,
                              __nv_bfloat16* __restrict__ hi,
                              __nv_bfloat16* __restrict__ lo, int K, int N)
{
    __shared__ float t[32][33];
    int k0 = blockIdx.y * 32, n0 = blockIdx.x * 32;
    int tx = threadIdx.x, ty = threadIdx.y;   // block (32,8)
#pragma unroll
    for (int i = 0; i < 32; i += 8)
        t[ty + i][tx] = W[(size_t)(k0 + ty + i) * N + n0 + tx];
    __syncthreads();
#pragma unroll
    for (int i = 0; i < 32; i += 8) {
        float v = t[tx][ty + i];
        size_t o = (size_t)(n0 + ty + i) * K + k0 + tx;
        __nv_bfloat16 h = __float2bfloat16(v);
        hi[o] = h;
        lo[o] = __float2bfloat16(v - __bfloat162float(h));
    }
}

// ---------------- mma.sync bf16 split GEMM ------------------------------------
#define GBM 128
#define GBN 64
#define GBK 64
#define KPAD 72
#define OFF_AH 0
#define OFF_AL (128 * KPAD * 2)
#define OFF_BH (2 * 128 * KPAD * 2)
#define OFF_BL (2 * 128 * KPAD * 2 + 64 * KPAD * 2)
#define GSMEM  (2 * 128 * KPAD * 2 + 2 * 64 * KPAD * 2)   // 55296 B

__global__ void __launch_bounds__(256)
gemm_mma_kernel(const __nv_bfloat16* __restrict__ Ahi,
                const __nv_bfloat16* __restrict__ Alo,
                const __nv_bfloat16* __restrict__ Bhi,
                const __nv_bfloat16* __restrict__ Blo,
                const float* __restrict__ bias,
                float* __restrict__ Cm,
                int N, int K)
{
    extern __shared__ __align__(16) unsigned char smem[];
    __nv_bfloat16* sAh = (__nv_bfloat16*)(smem + OFF_AH);
    __nv_bfloat16* sAl = (__nv_bfloat16*)(smem + OFF_AL);
    __nv_bfloat16* sBh = (__nv_bfloat16*)(smem + OFF_BH);
    __nv_bfloat16* sBl = (__nv_bfloat16*)(smem + OFF_BL);
    const uint32_t sb = smem_u32(smem);

    const int tid  = threadIdx.x;
    const int lane = tid & 31;
    const int w    = tid >> 5;
    const int m_base = (w & 3) * 32;
    const int n_base = (w >> 2) * 32;

    const int m0 = blockIdx.y * GBM;
    const int n0 = blockIdx.x * GBN;

    float d[2][4][4];
#pragma unroll
    for (int i = 0; i < 2; i++)
#pragma unroll
        for (int j = 0; j < 4; j++)
#pragma unroll
            for (int r = 0; r < 4; r++) d[i][j][r] = 0.f;

    const int a_m   = m_base + (lane & 7) + ((lane >> 3) & 1) * 8;
    const int a_khi = (lane >> 4) * 8;
    const int b_g   = lane >> 3;
    const int b_n8  = (b_g >> 1) * 8 + (lane & 7);
    const int b_k8  = (b_g & 1) * 8;

    for (int k0 = 0; k0 < K; k0 += GBK) {
#pragma unroll
        for (int it = 0; it < 4; it++) {
            int u = tid + it * 256;
            int row = u >> 3, c8 = u & 7;
            size_t g = (size_t)(m0 + row) * K + k0 + c8 * 8;
            int s = row * KPAD + c8 * 8;
            *(uint4*)(sAh + s) = *(const uint4*)(Ahi + g);
            *(uint4*)(sAl + s) = *(const uint4*)(Alo + g);
        }
#pragma unroll
        for (int it = 0; it < 2; it++) {
            int u = tid + it * 256;
            int row = u >> 3, c8 = u & 7;
            size_t g = (size_t)(n0 + row) * K + k0 + c8 * 8;
            int s = row * KPAD + c8 * 8;
            *(uint4*)(sBh + s) = *(const uint4*)(Bhi + g);
            *(uint4*)(sBl + s) = *(const uint4*)(Blo + g);
        }
        __syncthreads();

#pragma unroll
        for (int ks = 0; ks < 4; ks++) {
            const int koff = ks * 16;
            uint32_t ah[2][4], al[2][4], bh[4][2], bl[4][2];
#pragma unroll
            for (int mf = 0; mf < 2; mf++) {
                uint32_t off = (uint32_t)((a_m + mf * 16) * KPAD + koff + a_khi) * 2;
                ldsm_x4(ah[mf], sb + OFF_AH + off);
                ldsm_x4(al[mf], sb + OFF_AL + off);
            }
#pragma unroll
            for (int pr = 0; pr < 2; pr++) {
                uint32_t off = (uint32_t)((n_base + pr * 16 + b_n8) * KPAD + koff + b_k8) * 2;
                uint32_t rh[4], rl[4];
                ldsm_x4(rh, sb + OFF_BH + off);
                ldsm_x4(rl, sb + OFF_BL + off);
                bh[pr * 2 + 0][0] = rh[0]; bh[pr * 2 + 0][1] = rh[1];
                bh[pr * 2 + 1][0] = rh[2]; bh[pr * 2 + 1][1] = rh[3];
                bl[pr * 2 + 0][0] = rl[0]; bl[pr * 2 + 0][1] = rl[1];
                bl[pr * 2 + 1][0] = rl[2]; bl[pr * 2 + 1][1] = rl[3];
            }
#pragma unroll
            for (int mf = 0; mf < 2; mf++)
#pragma unroll
                for (int nf = 0; nf < 4; nf++) {
                    mma_bf16(d[mf][nf], ah[mf], bh[nf]);
                    mma_bf16(d[mf][nf], ah[mf], bl[nf]);
                    mma_bf16(d[mf][nf], al[mf], bh[nf]);
                }
        }
        __syncthreads();
    }

#pragma unroll
    for (int mf = 0; mf < 2; mf++) {
#pragma unroll
        for (int nf = 0; nf < 4; nf++) {
            int row = m0 + m_base + mf * 16 + (lane >> 2);
            int col = n0 + n_base + nf * 8 + 2 * (lane & 3);
            float bx = bias[col], by = bias[col + 1];
            float2 v0 = {d[mf][nf][0] + bx, d[mf][nf][1] + by};
            float2 v1 = {d[mf][nf][2] + bx, d[mf][nf][3] + by};
            *(float2*)&Cm[(size_t)row * N + col]       = v0;
            *(float2*)&Cm[(size_t)(row + 8) * N + col] = v1;
        }
    }
}

// ---------------- RoPE + scatter + bf16 hi/lo split ---------------------------
// qkv [B,T,3C] -> g_qh/ql (RoPE, pre-scaled 1/8), g_kh/kl (RoPE), g_vh/vl.
__global__ void rope_split_kernel(const float* __restrict__ qkv,
                                  const float* __restrict__ cosT,
                                  const float* __restrict__ sinT)
{
    int idx = blockIdx.x * blockDim.x + threadIdx.x;
    const int total = BB * HH * TT * (DD / 2);
    if (idx >= total) return;

    int i  = idx & 31;
    int t  = (idx >> 5) & (TT - 1);
    int hh = (idx >> 5) / TT;
    int h  = hh & (HH - 1);
    int b  = hh >> 4;

    float c = cosT[t * 32 + i];
    float s = sinT[t * 32 + i];

    const float* base = qkv + (size_t)(b * TT + t) * C3 + h * DD;
    size_t oBase = ((size_t)(b * HH + h) * TT + t) * DD + 2 * i;

    uint32_t hi, lo;
    float q1 = base[2 * i], q2 = base[2 * i + 1];
    split2((q1 * c - q2 * s) * 0.125f, (q1 * s + q2 * c) * 0.125f, hi, lo);
    *(uint32_t*)&g_qh[oBase] = hi;
    *(uint32_t*)&g_ql[oBase] = lo;

    float k1 = base[CC + 2 * i], k2 = base[CC + 2 * i + 1];
    split2(k1 * c - k2 * s, k1 * s + k2 * c, hi, lo);
    *(uint32_t*)&g_kh[oBase] = hi;
    *(uint32_t*)&g_kl[oBase] = lo;

    split2(base[2 * CC + 2 * i], base[2 * CC + 2 * i + 1], hi, lo);
    *(uint32_t*)&g_vh[oBase] = hi;
    *(uint32_t*)&g_vl[oBase] = lo;
}

// ---------------- tensor-core causal flash attention --------------------------
// BQ=128, BKV=64, 8 warps x 16 q-rows. Q frags register-resident; K/V per chunk.
#define FKP 72
#define F_QH 0
#define F_QL 18432
#define F_KH 0
#define F_KL 9216
#define F_VH 18432
#define F_VL 27648
#define FLASH_SMEM 36864

__global__ void __launch_bounds__(256)
flash_mma_kernel(const __nv_bfloat16* __restrict__ Qh,
                 const __nv_bfloat16* __restrict__ Ql,
                 const __nv_bfloat16* __restrict__ Kh,
                 const __nv_bfloat16* __restrict__ Kl,
                 const __nv_bfloat16* __restrict__ Vh,
                 const __nv_bfloat16* __restrict__ Vl)
{
    extern __shared__ __align__(16) unsigned char smem[];
    const uint32_t sb = smem_u32(smem);
    const int tid  = threadIdx.x;
    const int lane = tid & 31;
    const int w    = tid >> 5;

    const int qt = gridDim.x - 1 - blockIdx.x;   // heavy tiles first
    const int q0 = qt * 128;
    const int bh = blockIdx.y;
    const size_t gbase = (size_t)bh * TT * DD;

    // ---- load Q tile (hi/lo) into smem ----
#pragma unroll
    for (int it = 0; it < 4; it++) {
        int u = tid + it * 256;                  // 0..1023
        int row = u >> 3, c8 = (u & 7) * 8;
        size_t g = gbase + (size_t)(q0 + row) * DD + c8;
        int s = row * FKP + c8;
        *(uint4*)(smem + F_QH + s * 2) = *(const uint4*)(Qh + g);
        *(uint4*)(smem + F_QL + s * 2) = *(const uint4*)(Ql + g);
    }
    __syncthreads();

    // ---- Q fragments into registers ----
    const int a_m   = w * 16 + (lane & 7) + ((lane >> 3) & 1) * 8;
    const int a_khi = (lane >> 4) * 8;
    uint32_t qh[4][4], ql[4][4];
#pragma unroll
    for (int ks = 0; ks < 4; ks++) {
        uint32_t off = (uint32_t)(a_m * FKP + ks * 16 + a_khi) * 2;
        ldsm_x4(qh[ks], sb + F_QH + off);
        ldsm_x4(ql[ks], sb + F_QL + off);
    }
    __syncthreads();   // done with Q smem; reuse for K/V

    const int b_g   = lane >> 3;
    const int b_n8  = (b_g >> 1) * 8 + (lane & 7);
    const int b_k8  = (b_g & 1) * 8;
    const int v_r8  = (b_g & 1) * 8 + (lane & 7);
    const int v_c8  = (b_g >> 1) * 8;

    float o[8][4];
#pragma unroll
    for (int nf = 0; nf < 8; nf++)
#pragma unroll
        for (int j = 0; j < 4; j++) o[nf][j] = 0.f;
    float m0 = -1e30f, m1 = -1e30f, l0 = 0.f, l1 = 0.f;

    const int r0g = q0 + w * 16 + (lane >> 2);
    const int nchunk = 2 * qt + 2;

    for (int ch = 0; ch < nchunk; ch++) {
        const int kv0 = ch * 64;
        __syncthreads();   // previous chunk's smem reads done
#pragma unroll
        for (int it = 0; it < 2; it++) {
            int u = tid + it * 256;              // 0..511
            int row = u >> 3, c8 = (u & 7) * 8;
            size_t g = gbase + (size_t)(kv0 + row) * DD + c8;
            int s = (row * FKP + c8) * 2;
            *(uint4*)(smem + F_KH + s) = *(const uint4*)(Kh + g);
            *(uint4*)(smem + F_KL + s) = *(const uint4*)(Kl + g);
            *(uint4*)(smem + F_VH + s) = *(const uint4*)(Vh + g);
            *(uint4*)(smem + F_VL + s) = *(const uint4*)(Vl + g);
        }
        __syncthreads();

        // ---- S = Q K^T (3-term split) ----
        float s4[8][4];
#pragma unroll
        for (int nf = 0; nf < 8; nf++)
#pragma unroll
            for (int j = 0; j < 4; j++) s4[nf][j] = 0.f;

#pragma unroll
        for (int ks = 0; ks < 4; ks++) {
#pragma unroll
            for (int pr = 0; pr < 4; pr++) {
                uint32_t off = (uint32_t)((pr * 16 + b_n8) * FKP + ks * 16 + b_k8) * 2;
                uint32_t kh4[4], kl4[4];
                ldsm_x4(kh4, sb + F_KH + off);
                ldsm_x4(kl4, sb + F_KL + off);
                uint32_t bh0[2] = {kh4[0], kh4[1]}, bh1[2] = {kh4[2], kh4[3]};
                uint32_t bl0[2] = {kl4[0], kl4[1]}, bl1[2] = {kl4[2], kl4[3]};
                mma_bf16(s4[2 * pr], qh[ks], bh0);
                mma_bf16(s4[2 * pr], qh[ks], bl0);
                mma_bf16(s4[2 * pr], ql[ks], bh0);
                mma_bf16(s4[2 * pr + 1], qh[ks], bh1);
                mma_bf16(s4[2 * pr + 1], qh[ks], bl1);
                mma_bf16(s4[2 * pr + 1], ql[ks], bh1);
            }
        }

        // ---- causal mask (only last two chunks of this tile) ----
        if (ch >= 2 * qt) {
#pragma unroll
            for (int nf = 0; nf < 8; nf++) {
                int cbase = kv0 + nf * 8 + (lane & 3) * 2;
#pragma unroll
                for (int j = 0; j < 4; j++) {
                    int col = cbase + (j & 1);
                    int row = r0g + ((j >> 1) << 3);
                    if (col > row) s4[nf][j] = -1e30f;
                }
            }
        }

        // ---- online softmax ----
        float mx0 = -1e30f, mx1 = -1e30f;
#pragma unroll
        for (int nf = 0; nf < 8; nf++) {
            mx0 = fmaxf(mx0, fmaxf(s4[nf][0], s4[nf][1]));
            mx1 = fmaxf(mx1, fmaxf(s4[nf][2], s4[nf][3]));
        }
        mx0 = fmaxf(mx0, __shfl_xor_sync(0xffffffffu, mx0, 1));
        mx0 = fmaxf(mx0, __shfl_xor_sync(0xffffffffu, mx0, 2));
        mx1 = fmaxf(mx1, __shfl_xor_sync(0xffffffffu, mx1, 1));
        mx1 = fmaxf(mx1, __shfl_xor_sync(0xffffffffu, mx1, 2));
        float mn0 = fmaxf(m0, mx0), mn1 = fmaxf(m1, mx1);
        float al0 = __expf(m0 - mn0), al1 = __expf(m1 - mn1);
        float sum0 = 0.f, sum1 = 0.f;
#pragma unroll
        for (int nf = 0; nf < 8; nf++) {
            s4[nf][0] = __expf(s4[nf][0] - mn0);
            s4[nf][1] = __expf(s4[nf][1] - mn0);
            s4[nf][2] = __expf(s4[nf][2] - mn1);
            s4[nf][3] = __expf(s4[nf][3] - mn1);
            sum0 += s4[nf][0] + s4[nf][1];
            sum1 += s4[nf][2] + s4[nf][3];
        }
        sum0 += __shfl_xor_sync(0xffffffffu, sum0, 1);
        sum0 += __shfl_xor_sync(0xffffffffu, sum0, 2);
        sum1 += __shfl_xor_sync(0xffffffffu, sum1, 1);
        sum1 += __shfl_xor_sync(0xffffffffu, sum1, 2);
        l0 = l0 * al0 + sum0;  m0 = mn0;
        l1 = l1 * al1 + sum1;  m1 = mn1;
#pragma unroll
        for (int nf = 0; nf < 8; nf++) {
            o[nf][0] *= al0; o[nf][1] *= al0;
            o[nf][2] *= al1; o[nf][3] *= al1;
        }

        // ---- O += P V (3-term split, P from registers) ----
#pragma unroll
        for (int ks = 0; ks < 4; ks++) {
            uint32_t pa_h[4], pa_l[4];
            split2(s4[2 * ks][0],     s4[2 * ks][1],     pa_h[0], pa_l[0]);
            split2(s4[2 * ks][2],     s4[2 * ks][3],     pa_h[1], pa_l[1]);
            split2(s4[2 * ks + 1][0], s4[2 * ks + 1][1], pa_h[2], pa_l[2]);
            split2(s4[2 * ks + 1][2], s4[2 * ks + 1][3], pa_h[3], pa_l[3]);
#pragma unroll
            for (int pr = 0; pr < 4; pr++) {
                uint32_t off = (uint32_t)((ks * 16 + v_r8) * FKP + pr * 16 + v_c8) * 2;
                uint32_t vh4[4], vl4[4];
                ldsm_x4_t(vh4, sb + F_VH + off);
                ldsm_x4_t(vl4, sb + F_VL + off);
                uint32_t bh0[2] = {vh4[0], vh4[1]}, bh1[2] = {vh4[2], vh4[3]};
                uint32_t bl0[2] = {vl4[0], vl4[1]}, bl1[2] = {vl4[2], vl4[3]};
                mma_bf16(o[2 * pr], pa_h, bh0);
                mma_bf16(o[2 * pr], pa_h, bl0);
                mma_bf16(o[2 * pr], pa_l, bh0);
                mma_bf16(o[2 * pr + 1], pa_h, bh1);
                mma_bf16(o[2 * pr + 1], pa_h, bl1);
                mma_bf16(o[2 * pr + 1], pa_l, bh1);
            }
        }
    }

    // ---- epilogue: O /= l, write bf16 hi/lo to [B,T,C] ----
    float inv0 = 1.f / l0, inv1 = 1.f / l1;
    int b = bh >> 4, h = bh & 15;
    size_t base0 = ((size_t)(b * TT + r0g)) * CC + h * DD;
    size_t base1 = ((size_t)(b * TT + r0g + 8)) * CC + h * DD;
#pragma unroll
    for (int nf = 0; nf < 8; nf++) {
        int c = nf * 8 + (lane & 3) * 2;
        uint32_t hi, lo;
        split2(o[nf][0] * inv0, o[nf][1] * inv0, hi, lo);
        *(uint32_t*)&g_yhi[base0 + c] = hi;
        *(uint32_t*)&g_ylo[base0 + c] = lo;
        split2(o[nf][2] * inv1, o[nf][3] * inv1, hi, lo);
        *(uint32_t*)&g_yhi[base1 + c] = hi;
        *(uint32_t*)&g_ylo[base1 + c] = lo;
    }
}

// ---------------- launcher ----------------------------------------------------
extern "C" void kernel_launch(void* const* d_in, const int* in_sizes, int n_in,
                              void* d_out, int out_size)
{
    const float* x     = (const float*)d_in[0];
    const float* Wqkv  = (const float*)d_in[1];
    const float* bqkv  = (const float*)d_in[2];
    const float* Wproj = (const float*)d_in[3];
    const float* bproj = (const float*)d_in[4];
    const float* cosT  = (const float*)d_in[5];
    const float* sinT  = (const float*)d_in[6];
    float* out = (float*)d_out;

    float* qkv;
    __nv_bfloat16 *xhi, *xlo, *wqhi, *wqlo, *wphi, *wplo, *yhi, *ylo;
    __nv_bfloat16 *qh, *ql, *kh, *kl, *vh, *vl;
    cudaGetSymbolAddress((void**)&qkv,  g_qkv);
    cudaGetSymbolAddress((void**)&xhi,  g_xhi);
    cudaGetSymbolAddress((void**)&xlo,  g_xlo);
    cudaGetSymbolAddress((void**)&wqhi, g_wqhi);
    cudaGetSymbolAddress((void**)&wqlo, g_wqlo);
    cudaGetSymbolAddress((void**)&wphi, g_wphi);
    cudaGetSymbolAddress((void**)&wplo, g_wplo);
    cudaGetSymbolAddress((void**)&yhi,  g_yhi);
    cudaGetSymbolAddress((void**)&ylo,  g_ylo);
    cudaGetSymbolAddress((void**)&qh,   g_qh);
    cudaGetSymbolAddress((void**)&ql,   g_ql);
    cudaGetSymbolAddress((void**)&kh,   g_kh);
    cudaGetSymbolAddress((void**)&kl,   g_kl);
    cudaGetSymbolAddress((void**)&vh,   g_vh);
    cudaGetSymbolAddress((void**)&vl,   g_vl);

    static bool attr_set = false;
    if (!attr_set) {
        cudaFuncSetAttribute(gemm_mma_kernel,
                             cudaFuncAttributeMaxDynamicSharedMemorySize, GSMEM);
        cudaFuncSetAttribute(flash_mma_kernel,
                             cudaFuncAttributeMaxDynamicSharedMemorySize, FLASH_SMEM);
        attr_set = true;
    }

    // pre-pass: split x; transpose+split weights
    split_kernel<<<(MM * CC + 255) / 256, 256>>>(x, xhi, xlo, MM * CC);
    tsplit_kernel<<<dim3(C3 / 32, CC / 32), dim3(32, 8)>>>(Wqkv, wqhi, wqlo, CC, C3);
    tsplit_kernel<<<dim3(CC / 32, CC / 32), dim3(32, 8)>>>(Wproj, wphi, wplo, CC, CC);

    // 1) QKV projection (tensor cores)
    gemm_mma_kernel<<<dim3(C3 / GBN, MM / GBM), 256, GSMEM>>>(
        xhi, xlo, wqhi, wqlo, bqkv, qkv, C3, CC);

    // 2) RoPE + scatter + bf16 split (Q pre-scaled by 1/8)
    {
        int total = BB * HH * TT * (DD / 2);
        rope_split_kernel<<<(total + 255) / 256, 256>>>(qkv, cosT, sinT);
    }

    // 3) tensor-core causal flash attention
    flash_mma_kernel<<<dim3(TT / 128, BB * HH), 256, FLASH_SMEM>>>(
        qh, ql, kh, kl, vh, vl);

    // 4) output projection (tensor cores)
    gemm_mma_kernel<<<dim3(CC / GBN, MM / GBM), 256, GSMEM>>>(
        yhi, ylo, wphi, wplo, bproj, out, CC, CC);
}